// round 7
// baseline (speedup 1.0000x reference)
#include <cuda_runtime.h>
#include <cuda_bf16.h>
#include <cooperative_groups.h>

namespace cg = cooperative_groups;

#define Bn 8
#define Nn 2048
#define Mn 256
#define Qn 16384
#define Dn 32
#define Rn 16
#define Kn 16
#define Hn 64
#define LAMf 5.0f
#define CG_ITERS 20

#define CLUSTER_ARRIVE() asm volatile("barrier.cluster.arrive.aligned;" ::: "memory")
#define CLUSTER_WAIT() asm volatile("barrier.cluster.wait.aligned;" ::: "memory")

// ---------------- device scratch ----------------
__device__ float g_gvec[Bn * Dn];
__device__ float g_c0s[Bn * Mn * Dn];
__device__ float g_cs[Bn * Mn * Dn];

__device__ __forceinline__ float dot4(float4 a, float4 b) {
    return a.x * b.x + a.y * b.y + a.z * b.z + a.w * b.w;
}

// ---------------- global feature g[b,:] ----------------
__global__ __launch_bounds__(256) void k_g(const float* __restrict__ xs,
                                           const float* __restrict__ us,
                                           const float* __restrict__ Wg1,
                                           const float* __restrict__ bg1,
                                           const float* __restrict__ Wg2,
                                           const float* __restrict__ bg2) {
    __shared__ float part[256];
    __shared__ float gmean[Hn];
    int b = blockIdx.x;
    int t = threadIdx.x;
    int h = t & 63, grp = t >> 6;
    float w0 = Wg1[h], w1 = Wg1[Hn + h], bb = bg1[h];
    float acc = 0.f;
    for (int n = grp; n < Nn; n += 4) {
        float v = fmaf(xs[b * Nn + n], w0, fmaf(us[b * Nn + n], w1, bb));
        acc += fmaxf(v, 0.f);
    }
    part[t] = acc;
    __syncthreads();
    if (t < Hn)
        gmean[t] = (part[t] + part[t + 64] + part[t + 128] + part[t + 192]) * (1.0f / (float)Nn);
    __syncthreads();
    if (t < Dn) {
        float a = bg2[t];
#pragma unroll
        for (int hh = 0; hh < Hn; hh++) a = fmaf(gmean[hh], Wg2[hh * Dn + t], a);
        g_gvec[b * Dn + t] = a;
    }
}

// ---------------- encoder: 4 m per block, 256 threads ----------------
__global__ __launch_bounds__(256) void k_encode(const float* __restrict__ xs,
                                                const float* __restrict__ us,
                                                const float* __restrict__ centers,
                                                const float* __restrict__ W1,
                                                const float* __restrict__ b1,
                                                const float* __restrict__ W2,
                                                const float* __restrict__ b2,
                                                const float* __restrict__ W3,
                                                const float* __restrict__ b3,
                                                const int* __restrict__ idx,
                                                float* __restrict__ out_c0) {
    __shared__ float W2s[Hn * Hn];
    __shared__ float h1[4][Kn][Hn];
    __shared__ float sx[4][Kn], su[4][Kn];
    __shared__ float hm[4][Hn];
    int blk = blockIdx.x;  // 512 = 8 b x 64 m-groups
    int b = blk >> 6;
    int mbase = (blk & 63) << 2;
    int t = threadIdx.x;
    int gr = t >> 6, h = t & 63;

    for (int i = t; i < Hn * Hn; i += 256) W2s[i] = W2[i];
    if (t < 64) {
        int gr2 = t >> 4, k = t & 15;
        int id = idx[(mbase + gr2) * Kn + k];
        sx[gr2][k] = xs[b * Nn + id];
        su[gr2][k] = us[b * Nn + id];
    }
    __syncthreads();

    int m = mbase + gr;
    const float invR = (float)Mn / 1.5f;
    float w1a = W1[h], w1b = W1[Hn + h], bb1 = b1[h];
    float cm = centers[m];
#pragma unroll
    for (int k = 0; k < Kn; k++) {
        float rel = (sx[gr][k] - cm) * invR;
        h1[gr][k][h] = fmaxf(fmaf(rel, w1a, fmaf(su[gr][k], w1b, bb1)), 0.f);
    }
    __syncthreads();

    float bb2 = b2[h];
    float accv[Kn];
#pragma unroll
    for (int k = 0; k < Kn; k++) accv[k] = bb2;
#pragma unroll
    for (int hh = 0; hh < Hn; hh += 4) {
        float wa = W2s[(hh + 0) * Hn + h];
        float wb = W2s[(hh + 1) * Hn + h];
        float wc = W2s[(hh + 2) * Hn + h];
        float wd = W2s[(hh + 3) * Hn + h];
#pragma unroll
        for (int k = 0; k < Kn; k++) {
            float4 hv = *(const float4*)&h1[gr][k][hh];
            accv[k] = fmaf(hv.x, wa, accv[k]);
            accv[k] = fmaf(hv.y, wb, accv[k]);
            accv[k] = fmaf(hv.z, wc, accv[k]);
            accv[k] = fmaf(hv.w, wd, accv[k]);
        }
    }
    float ssum = 0.f;
#pragma unroll
    for (int k = 0; k < Kn; k++) ssum += fmaxf(accv[k], 0.f);
    hm[gr][h] = ssum * (1.0f / (float)Kn);
    __syncthreads();

    if (h < Dn) {
        float a = b3[h];
#pragma unroll
        for (int hh = 0; hh < Hn; hh++) a = fmaf(hm[gr][hh], W3[hh * Dn + h], a);
        a += g_gvec[b * Dn + h];
        int gi = (b * Mn + m) * Dn + h;
        g_c0s[gi] = a;
        out_c0[gi] = a;
    }
}

// ==================== CG glue: 4 clusters x 8 CTAs, 2 batches/cluster ====================
// Thread layout (512): t = m*16 + dq*2 + b   (m=node/team 0..31, dq=d-quad 0..7, b=local batch 0..1)
// smem offsets (floats):
#define OFF_RS 0
#define OFF_RD 16896
#define OFF_P 33792    // [2][34][32]
#define OFF_R 35968    // [2][34][32]
#define OFF_RE 38144   // [2][33][16]
#define OFF_REDA 39200 // [2][16]
#define OFF_REDB 39232 // [2][16]
#define OFF_REDC 39264 // [2][16]
#define OFF_SLOTS 39296  // [4][8]: rows 0,1 = rs(b0,b1); 2,3 = rp(b0,b1)
#define OFF_SRE2 39328   // [2][8]
#define CG_SM_FLOATS 39344

__global__ void __cluster_dims__(8, 1, 1) __launch_bounds__(512, 1)
    k_cg(const float* __restrict__ Rsrc, const float* __restrict__ Rdst,
         float* __restrict__ out_c) {
    extern __shared__ float smf[];
    float4* Rs4 = (float4*)(smf + OFF_RS);
    float4* Rd4 = (float4*)(smf + OFF_RD);
    float4* p4s = (float4*)(smf + OFF_P);
    float4* r4s = (float4*)(smf + OFF_R);
    float* re_sm = smf + OFF_RE;
    float* redA = smf + OFF_REDA;
    float* redB = smf + OFF_REDB;
    float* redC = smf + OFF_REDC;
    float* slots = smf + OFF_SLOTS;
    float* sre2 = smf + OFF_SRE2;

    cg::cluster_group cl = cg::this_cluster();
    const int t = threadIdx.x;
    const int l = t & 31, w = t >> 5;
    const int c = blockIdx.x >> 3;  // cluster -> batches 2c, 2c+1
    const int s = blockIdx.x & 7;   // rank: nodes [32s, 32s+32)
    const int m = t >> 4;           // own node / team id
    const int dq = (t >> 1) & 7;
    const int b = t & 1;
    const float4 z4 = make_float4(0.f, 0.f, 0.f, 0.f);

    // ---- prologue: R slice + p=c0 (ext domain, zero halo at global boundary) ----
    const float4* Rsg = (const float4*)Rsrc;
    const float4* Rdg = (const float4*)Rdst;
    for (int i4 = t; i4 < 33 * 128; i4 += 512) {
        int le = i4 >> 7, rem = i4 & 127;
        int ge = s * 32 - 1 + le;
        bool ok = (ge >= 0) && (ge < Mn - 1);
        Rs4[i4] = ok ? Rsg[ge * 128 + rem] : z4;
        Rd4[i4] = ok ? Rdg[ge * 128 + rem] : z4;
    }
    const float4* c0g = (const float4*)g_c0s;
    for (int i4 = t; i4 < 544; i4 += 512) {
        int bb = (i4 >= 272) ? 1 : 0;
        int rem = i4 - bb * 272;
        int slot = rem >> 3, j = rem & 7;
        int gm = s * 32 - 1 + slot;
        p4s[i4] = (gm >= 0 && gm < Mn) ? c0g[((c * 2 + bb) * Mn + gm) * 8 + j] : z4;
        r4s[i4] = z4;
    }
    __syncthreads();

    float4 x4, Ap, pown;
    float rs_[2], pp[2];

    // ---- applyA: phase A -> (optional re2 reduce+scatter+arrive | syncthreads) -> phase B
    auto applyA = [&](bool with_re2) {
        float re2 = 0.f;
        {
            int le = m;  // team == node index
            float4 p0 = p4s[b * 272 + le * 8 + dq];
            float4 p1 = p4s[b * 272 + le * 8 + 8 + dq];
            const float4* rsrow = Rs4 + le * 128 + dq;
            const float4* rdrow = Rd4 + le * 128 + dq;
#pragma unroll
            for (int rho = 0; rho < 16; rho++) {
                float a = dot4(rsrow[rho * 8], p0) - dot4(rdrow[rho * 8], p1);
                a += __shfl_xor_sync(0xffffffffu, a, 2);
                a += __shfl_xor_sync(0xffffffffu, a, 4);
                a += __shfl_xor_sync(0xffffffffu, a, 8);
                if ((t & 14) == 0) {  // dq == 0
                    re_sm[b * 528 + le * 16 + rho] = a;
                    if (le >= 1) re2 += a * a;  // each global edge counted once per cluster
                }
            }
        }
        if (w < 8) {  // extra edge le=32, rho = team id (0..15); per-warp uniform
            int rho = m;
            float4 p0 = p4s[b * 272 + 32 * 8 + dq];
            float4 p1 = p4s[b * 272 + 33 * 8 + dq];
            float a = dot4(Rs4[32 * 128 + rho * 8 + dq], p0) -
                      dot4(Rd4[32 * 128 + rho * 8 + dq], p1);
            a += __shfl_xor_sync(0xffffffffu, a, 2);
            a += __shfl_xor_sync(0xffffffffu, a, 4);
            a += __shfl_xor_sync(0xffffffffu, a, 8);
            if ((t & 14) == 0) {
                re_sm[b * 528 + 32 * 16 + rho] = a;
                re2 += a * a;
            }
        }
        if (with_re2) {
            float v = re2;
            v += __shfl_xor_sync(0xffffffffu, v, 2);
            v += __shfl_xor_sync(0xffffffffu, v, 4);
            v += __shfl_xor_sync(0xffffffffu, v, 8);
            v += __shfl_xor_sync(0xffffffffu, v, 16);
            if (l < 2) redC[l * 16 + w] = v;
            __syncthreads();  // also fences re_sm for phase B
            if (w == 0) {
                int row = l >> 3, col = l & 7;
                float v2 = 0.f;
                if (row < 2) v2 = redC[row * 16 + col] + redC[row * 16 + col + 8];
                v2 += __shfl_xor_sync(0xffffffffu, v2, 1);
                v2 += __shfl_xor_sync(0xffffffffu, v2, 2);
                v2 += __shfl_xor_sync(0xffffffffu, v2, 4);
                if (col == 0 && row < 2) {
#pragma unroll
                    for (int rr = 0; rr < 8; rr++) {
                        float* rem = (float*)cl.map_shared_rank((void*)sre2, rr);
                        rem[row * 8 + s] = v2;
                    }
                }
            }
            CLUSTER_ARRIVE();  // release: re2 partials visible after peers' WAIT
        } else {
            __syncthreads();
        }
        // phase B: Ap for own node
        float4 acc = z4;
        const float* reb = re_sm + b * 528;
        const float4* rsc = Rs4 + (m + 1) * 128 + dq;
        const float4* rdc = Rd4 + m * 128 + dq;
#pragma unroll
        for (int rho = 0; rho < 16; rho++) {
            float wv = reb[(m + 1) * 16 + rho];
            float4 rv = rsc[rho * 8];
            acc.x = fmaf(rv.x, wv, acc.x);
            acc.y = fmaf(rv.y, wv, acc.y);
            acc.z = fmaf(rv.z, wv, acc.z);
            acc.w = fmaf(rv.w, wv, acc.w);
        }
#pragma unroll
        for (int rho = 0; rho < 16; rho++) {
            float wv = reb[m * 16 + rho];
            float4 rv = rdc[rho * 8];
            acc.x = fmaf(-rv.x, wv, acc.x);
            acc.y = fmaf(-rv.y, wv, acc.y);
            acc.z = fmaf(-rv.z, wv, acc.z);
            acc.w = fmaf(-rv.w, wv, acc.w);
        }
        pown = p4s[b * 272 + (m + 1) * 8 + dq];
        Ap.x = fmaf(LAMf, acc.x, pown.x);
        Ap.y = fmaf(LAMf, acc.y, pown.y);
        Ap.z = fmaf(LAMf, acc.z, pown.z);
        Ap.w = fmaf(LAMf, acc.w, pown.w);
    };

    auto reduce2_arrive = [&](float vrs, float vrp) {
#pragma unroll
        for (int o = 2; o <= 16; o <<= 1) {
            vrs += __shfl_xor_sync(0xffffffffu, vrs, o);
            vrp += __shfl_xor_sync(0xffffffffu, vrp, o);
        }
        if (l < 2) {
            redA[l * 16 + w] = vrs;
            redB[l * 16 + w] = vrp;
        }
        __syncthreads();
        if (w == 0) {
            int row = l >> 3, col = l & 7;
            const float* arr = (row < 2) ? redA : redB;
            int bb2 = row & 1;
            float v2 = arr[bb2 * 16 + col] + arr[bb2 * 16 + col + 8];
            v2 += __shfl_xor_sync(0xffffffffu, v2, 1);
            v2 += __shfl_xor_sync(0xffffffffu, v2, 2);
            v2 += __shfl_xor_sync(0xffffffffu, v2, 4);
            if (col == 0) {
#pragma unroll
                for (int rr = 0; rr < 8; rr++) {
                    float* rem = (float*)cl.map_shared_rank((void*)slots, rr);
                    rem[row * 8 + s] = v2;
                }
            }
        }
        CLUSTER_ARRIVE();
    };

    auto fetch_halo = [&]() {
        if (t < 16) {
            int hb = t >> 3, j = t & 7;
            if (s > 0) {
                const float4* rem = (const float4*)cl.map_shared_rank((void*)(smf + OFF_R), s - 1);
                r4s[hb * 272 + j] = rem[hb * 272 + 32 * 8 + j];
            }
        } else if (t < 32) {
            int u = t - 16;
            int hb = u >> 3, j = u & 7;
            if (s < 7) {
                const float4* rem = (const float4*)cl.map_shared_rank((void*)(smf + OFF_R), s + 1);
                r4s[hb * 272 + 33 * 8 + j] = rem[hb * 272 + 1 * 8 + j];
            }
        }
    };

    // ---- init: x=c0, r=c0-A(c0), p=r, rs=|r|^2, pp=|p|^2=rs ----
    applyA(false);
    x4 = pown;
    float4 rown = make_float4(x4.x - Ap.x, x4.y - Ap.y, x4.z - Ap.z, x4.w - Ap.w);
    r4s[b * 272 + (m + 1) * 8 + dq] = rown;
    reduce2_arrive(dot4(rown, rown), 0.f);
    CLUSTER_WAIT();
#pragma unroll
    for (int bb = 0; bb < 2; bb++) {
        float sv = 0.f;
#pragma unroll
        for (int rr = 0; rr < 8; rr++) sv += slots[bb * 8 + rr];
        rs_[bb] = sv;
        pp[bb] = sv;
    }
    fetch_halo();
    __syncthreads();
    for (int i4 = t; i4 < 544; i4 += 512) p4s[i4] = r4s[i4];

    // ---- main loop ----
    for (int it = 0; it < CG_ITERS; it++) {
        __syncthreads();  // p4s ready
        applyA(true);     // ARRIVE(1) inside (before phase B)
        CLUSTER_WAIT();   // sync 1: sum(re^2) available
        float al[2];
#pragma unroll
        for (int bb = 0; bb < 2; bb++) {
            float sv = 0.f;
#pragma unroll
            for (int rr = 0; rr < 8; rr++) sv += sre2[bb * 8 + rr];
            float pap = pp[bb] + LAMf * sv;  // p.Ap = |p|^2 + LAM*|Bp|^2 (exact identity)
            al[bb] = rs_[bb] / (pap + 1e-12f);
        }
        float a_ = al[b];
        x4.x = fmaf(a_, pown.x, x4.x);
        x4.y = fmaf(a_, pown.y, x4.y);
        x4.z = fmaf(a_, pown.z, x4.z);
        x4.w = fmaf(a_, pown.w, x4.w);
        rown = r4s[b * 272 + (m + 1) * 8 + dq];
        rown.x = fmaf(-a_, Ap.x, rown.x);
        rown.y = fmaf(-a_, Ap.y, rown.y);
        rown.z = fmaf(-a_, Ap.z, rown.z);
        rown.w = fmaf(-a_, Ap.w, rown.w);
        r4s[b * 272 + (m + 1) * 8 + dq] = rown;

        reduce2_arrive(dot4(rown, rown), dot4(rown, pown));
        CLUSTER_WAIT();  // sync 2: rs_new, r.p
        float bt[2];
#pragma unroll
        for (int bb = 0; bb < 2; bb++) {
            float rsn = 0.f, rp = 0.f;
#pragma unroll
            for (int rr = 0; rr < 8; rr++) {
                rsn += slots[bb * 8 + rr];
                rp += slots[(2 + bb) * 8 + rr];
            }
            float beta = rsn / (rs_[bb] + 1e-12f);
            bt[bb] = beta;
            pp[bb] = rsn + 2.f * beta * rp + beta * beta * pp[bb];  // |p_new|^2
            rs_[bb] = rsn;
        }
        fetch_halo();
        __syncthreads();
        for (int i4 = t; i4 < 544; i4 += 512) {
            float beta = (i4 >= 272) ? bt[1] : bt[0];
            float4 rr = r4s[i4];
            float4 pv = p4s[i4];
            pv.x = fmaf(beta, pv.x, rr.x);
            pv.y = fmaf(beta, pv.y, rr.y);
            pv.z = fmaf(beta, pv.z, rr.z);
            pv.w = fmaf(beta, pv.w, rr.w);
            p4s[i4] = pv;
        }
    }

    // ---- epilogue ----
    int gm = s * 32 + m;
    int batch = c * 2 + b;
    ((float4*)g_cs)[(batch * Mn + gm) * 8 + dq] = x4;
    ((float4*)out_c)[(batch * Mn + gm) * 8 + dq] = x4;
}

// ---------------- decode ----------------
// support of w/phi: m in {q/64-1, q/64, q/64+1}; branchless clamped loads for MLP
__global__ __launch_bounds__(128) void k_decode(const float* __restrict__ phi,
                                                const float* __restrict__ w,
                                                float* __restrict__ out_s) {
    __shared__ float csm[3][Bn][Dn];
    int g = blockIdx.x;  // 512 groups of 32 q
    int qbase = g * 32;
    int mq = qbase >> 6;
    int mlo = mq - 1;
    int t = threadIdx.x;

    for (int i = t; i < 3 * Bn * Dn; i += 128) {
        int mi = i >> 8;
        int b = (i >> 5) & 7;
        int d = i & 31;
        int mm = mlo + mi;
        csm[mi][b][d] = (mm >= 0 && mm < Mn) ? g_cs[(b * Mn + mm) * Dn + d] : 0.f;
    }
    __syncthreads();

    int q = qbase + (t & 31);
    int bg = t >> 5;  // 0..3 -> batches bg, bg+4
    float acc0 = 0.f, acc1 = 0.f;

#pragma unroll
    for (int kk = 0; kk < 3; kk++) {
        int mm = mlo + kk;
        bool valid = (mm >= 0) && (mm < Mn);
        int mc = valid ? mm : 0;
        float wv = valid ? __ldg(&w[(size_t)mc * Qn + q]) : 0.f;
        const float4* ph = (const float4*)(phi + ((size_t)mc * Qn + q) * Dn);
        const float4* c0 = (const float4*)&csm[kk][bg][0];
        const float4* c1 = (const float4*)&csm[kk][bg + 4][0];
        float d0 = 0.f, d1 = 0.f;
#pragma unroll
        for (int j = 0; j < 8; j++) {
            float4 pv = __ldg(&ph[j]);
            d0 += dot4(pv, c0[j]);
            d1 += dot4(pv, c1[j]);
        }
        acc0 = fmaf(wv, d0, acc0);
        acc1 = fmaf(wv, d1, acc1);
    }
    out_s[bg * Qn + q] = acc0;
    out_s[(bg + 4) * Qn + q] = acc1;
}

// ---------------- launch ----------------
extern "C" void kernel_launch(void* const* d_in, const int* in_sizes, int n_in,
                              void* d_out, int out_size) {
    const float* xs = (const float*)d_in[0];
    const float* us = (const float*)d_in[1];
    const float* phi_q = (const float*)d_in[2];
    const float* w = (const float*)d_in[3];
    const float* centers = (const float*)d_in[4];
    const float* R_src = (const float*)d_in[5];
    const float* R_dst = (const float*)d_in[6];
    const float* W1 = (const float*)d_in[7];
    const float* b1 = (const float*)d_in[8];
    const float* W2 = (const float*)d_in[9];
    const float* b2 = (const float*)d_in[10];
    const float* W3 = (const float*)d_in[11];
    const float* b3 = (const float*)d_in[12];
    const float* Wg1 = (const float*)d_in[13];
    const float* bg1 = (const float*)d_in[14];
    const float* Wg2 = (const float*)d_in[15];
    const float* bg2 = (const float*)d_in[16];
    const int* idx = (const int*)d_in[17];

    float* out = (float*)d_out;
    float* out_s = out;                           // [B,Q,1]
    float* out_c0 = out + Bn * Qn;                // [B,M,D]
    float* out_c = out + Bn * Qn + Bn * Mn * Dn;  // [B,M,D]

    cudaFuncSetAttribute(k_cg, cudaFuncAttributeMaxDynamicSharedMemorySize,
                         CG_SM_FLOATS * (int)sizeof(float));

    k_g<<<Bn, 256>>>(xs, us, Wg1, bg1, Wg2, bg2);
    k_encode<<<512, 256>>>(xs, us, centers, W1, b1, W2, b2, W3, b3, idx, out_c0);
    k_cg<<<32, 512, CG_SM_FLOATS * sizeof(float)>>>(R_src, R_dst, out_c);
    k_decode<<<512, 128>>>(phi_q, w, out_s);
}